// round 3
// baseline (speedup 1.0000x reference)
#include <cuda_runtime.h>
#include <cstdint>

__device__ float g_lig_proj[512 * 512];
__device__ float g_rec_proj[512 * 512];

#define D 512
#define BM 64
#define BN 64
#define BK 32
#define NK (D / BK)
#define JBLK 64

// C[i,o] = sum_k A[i,k] * W[o, w_off + k]  (+ bias[o] for receptor)
// Double-buffered smem, float4 shared loads, 4x4 micro-tile, 256 threads.
__global__ __launch_bounds__(256) void proj_gemm_kernel(
    const float* __restrict__ lig,
    const float* __restrict__ rec,
    const float* __restrict__ W,
    const float* __restrict__ bias)
{
    __shared__ float As[2][BK][BM];   // As[buf][k][i]
    __shared__ float Bs[2][BK][BN];   // Bs[buf][k][o]

    const int z = blockIdx.z;
    const float* A = (z == 0) ? lig : rec;
    float* C = (z == 0) ? g_lig_proj : g_rec_proj;
    const int w_off_f4 = (z == 0) ? 0 : (D / 4);

    const int tx = threadIdx.x;  // 0..15
    const int ty = threadIdx.y;  // 0..15
    const int tid = ty * 16 + tx;
    const int i0 = blockIdx.y * BM;
    const int o0 = blockIdx.x * BN;

    // Tile is 64 rows x 8 float4-cols = 512 float4; 256 threads -> 2 each.
    const int lr0 = tid >> 3;          // 0..31
    const int lc  = tid & 7;           // float4-col 0..7
    const float4* A4 = reinterpret_cast<const float4*>(A);
    const float4* W4 = reinterpret_cast<const float4*>(W);

    float acc[4][4] = {};

    // Prologue: load tile 0 into buf 0
    {
        #pragma unroll
        for (int h = 0; h < 2; h++) {
            int r = lr0 + h * 32;
            float4 v = A4[(size_t)(i0 + r) * (D / 4) + lc];
            As[0][lc * 4 + 0][r] = v.x;
            As[0][lc * 4 + 1][r] = v.y;
            As[0][lc * 4 + 2][r] = v.z;
            As[0][lc * 4 + 3][r] = v.w;
        }
        #pragma unroll
        for (int h = 0; h < 2; h++) {
            int r = lr0 + h * 32;
            float4 v = W4[(size_t)(o0 + r) * (2 * D / 4) + w_off_f4 + lc];
            Bs[0][lc * 4 + 0][r] = v.x;
            Bs[0][lc * 4 + 1][r] = v.y;
            Bs[0][lc * 4 + 2][r] = v.z;
            Bs[0][lc * 4 + 3][r] = v.w;
        }
    }
    __syncthreads();

    int cur = 0;
    for (int t = 0; t < NK; t++) {
        // Issue global loads for the next tile (overlap with compute below)
        float4 va0, va1, vb0, vb1;
        if (t + 1 < NK) {
            const int kc4 = (t + 1) * (BK / 4);
            va0 = A4[(size_t)(i0 + lr0)      * (D / 4) + kc4 + lc];
            va1 = A4[(size_t)(i0 + lr0 + 32) * (D / 4) + kc4 + lc];
            vb0 = W4[(size_t)(o0 + lr0)      * (2 * D / 4) + w_off_f4 + kc4 + lc];
            vb1 = W4[(size_t)(o0 + lr0 + 32) * (2 * D / 4) + w_off_f4 + kc4 + lc];
        }

        // Compute on current buffer: float4 LDS for both fragments
        #pragma unroll
        for (int kk = 0; kk < BK; kk++) {
            float4 af = *reinterpret_cast<const float4*>(&As[cur][kk][ty * 4]);
            float4 bf = *reinterpret_cast<const float4*>(&Bs[cur][kk][tx * 4]);
            float a[4] = {af.x, af.y, af.z, af.w};
            float bq[4] = {bf.x, bf.y, bf.z, bf.w};
            #pragma unroll
            for (int u = 0; u < 4; u++)
                #pragma unroll
                for (int v = 0; v < 4; v++)
                    acc[u][v] += a[u] * bq[v];
        }

        if (t + 1 < NK) {
            int nxt = cur ^ 1;
            As[nxt][lc * 4 + 0][lr0] = va0.x;
            As[nxt][lc * 4 + 1][lr0] = va0.y;
            As[nxt][lc * 4 + 2][lr0] = va0.z;
            As[nxt][lc * 4 + 3][lr0] = va0.w;
            As[nxt][lc * 4 + 0][lr0 + 32] = va1.x;
            As[nxt][lc * 4 + 1][lr0 + 32] = va1.y;
            As[nxt][lc * 4 + 2][lr0 + 32] = va1.z;
            As[nxt][lc * 4 + 3][lr0 + 32] = va1.w;
            Bs[nxt][lc * 4 + 0][lr0] = vb0.x;
            Bs[nxt][lc * 4 + 1][lr0] = vb0.y;
            Bs[nxt][lc * 4 + 2][lr0] = vb0.z;
            Bs[nxt][lc * 4 + 3][lr0] = vb0.w;
            Bs[nxt][lc * 4 + 0][lr0 + 32] = vb1.x;
            Bs[nxt][lc * 4 + 1][lr0 + 32] = vb1.y;
            Bs[nxt][lc * 4 + 2][lr0 + 32] = vb1.z;
            Bs[nxt][lc * 4 + 3][lr0 + 32] = vb1.w;
            __syncthreads();
            cur = nxt;
        }
    }

    #pragma unroll
    for (int u = 0; u < 4; u++) {
        const int i = i0 + ty * 4 + u;
        #pragma unroll
        for (int v = 0; v < 4; v++) {
            const int o = o0 + tx * 4 + v;
            float val = acc[u][v];
            if (z == 1) val += bias[o];
            C[i * D + o] = val;
        }
    }
}

// out[i, j, :] = lig_proj[i, :] + rec_proj[j, :]
// Block = (one i, JBLK consecutive j's), 128 threads (one float4 column each).
// Batch-of-8 software pipeline: 8 in-flight rec loads, then 8 streaming stores.
__global__ __launch_bounds__(128) void pair_add_kernel(float4* __restrict__ out)
{
    const int c = threadIdx.x;            // 0..127 float4 column
    const int i = blockIdx.y;
    const int j0 = blockIdx.x * JBLK;

    const float4* lig = reinterpret_cast<const float4*>(g_lig_proj);
    const float4* rec = reinterpret_cast<const float4*>(g_rec_proj);

    const float4 a = lig[i * 128 + c];

    const float4* rp = rec + (size_t)j0 * 128 + c;
    float4* op = out + ((size_t)i * D + j0) * 128 + c;

    for (int jj = 0; jj < JBLK; jj += 8) {
        float4 r[8];
        #pragma unroll
        for (int u = 0; u < 8; u++)
            r[u] = __ldg(rp + (size_t)(jj + u) * 128);
        #pragma unroll
        for (int u = 0; u < 8; u++) {
            float4 o;
            o.x = a.x + r[u].x;
            o.y = a.y + r[u].y;
            o.z = a.z + r[u].z;
            o.w = a.w + r[u].w;
            __stcs(op + (size_t)(jj + u) * 128, o);
        }
    }
}

extern "C" void kernel_launch(void* const* d_in, const int* in_sizes, int n_in,
                              void* d_out, int out_size)
{
    const float* lig = (const float*)d_in[0];   // (512, 512)
    const float* rec = (const float*)d_in[1];   // (512, 512)
    const float* W   = (const float*)d_in[2];   // (512, 1024)
    const float* b   = (const float*)d_in[3];   // (512,)
    float* out = (float*)d_out;                 // (512, 512, 512)

    dim3 gblk(16, 16);
    dim3 ggrd(D / BN, D / BM, 2);   // 128 blocks, one wave
    proj_gemm_kernel<<<ggrd, gblk>>>(lig, rec, W, b);

    dim3 agrd(D / JBLK, D);         // 8 x 512 = 4096 blocks
    pair_add_kernel<<<agrd, 128>>>(reinterpret_cast<float4*>(out));
}

// round 4
// speedup vs baseline: 1.0368x; 1.0368x over previous
#include <cuda_runtime.h>
#include <cstdint>

__device__ float g_lig_proj[512 * 512];
__device__ float g_rec_proj[512 * 512];

#define D 512
#define BM 64
#define BN 64
#define BK 32
#define NKT (D / BK)
#define JBLK 64
#define IBLK 4

__device__ __forceinline__ uint32_t f2tf32(float x) {
    uint32_t r;
    asm("cvt.rna.tf32.f32 %0, %1;" : "=r"(r) : "f"(x));
    return r;
}

__device__ __forceinline__ void mma_tf32(float* d, const uint32_t* a, const uint32_t* b) {
    asm volatile(
        "mma.sync.aligned.m16n8k8.row.col.f32.tf32.tf32.f32 "
        "{%0,%1,%2,%3}, {%4,%5,%6,%7}, {%8,%9}, {%0,%1,%2,%3};"
        : "+f"(d[0]), "+f"(d[1]), "+f"(d[2]), "+f"(d[3])
        : "r"(a[0]), "r"(a[1]), "r"(a[2]), "r"(a[3]), "r"(b[0]), "r"(b[1]));
}

// C[i,o] = sum_k A[i,k] * W[o, w_off + k] (+ bias for receptor).
// tf32 tensor-core GEMM with hi/lo error compensation (3 MMAs per logical MMA).
// Block: 256 threads (8 warps, 2m x 4n), tile 64x64, BK=32.
// smem staged in fragment order: Sa[(mtile*4+ktile)*32+lane][4], Sb[(ntile*4+ktile)*32+lane][2].
__global__ __launch_bounds__(256) void proj_gemm_kernel(
    const float* __restrict__ lig,
    const float* __restrict__ rec,
    const float* __restrict__ W,
    const float* __restrict__ bias)
{
    __shared__ float Sa[BM * BK];   // 8KB, fragment-ordered
    __shared__ float Sb[BN * BK];   // 8KB, fragment-ordered

    const int z = blockIdx.z;
    const float* A = (z == 0) ? lig : rec;
    float* C = (z == 0) ? g_lig_proj : g_rec_proj;
    const int w_off_f4 = (z == 0) ? 0 : (D / 4);

    const int tid = threadIdx.x;
    const int lane = tid & 31;
    const int wid = tid >> 5;
    const int mwarp = wid >> 2;     // 0..1 -> 32 rows each
    const int nwarp = wid & 3;      // 0..3 -> 16 cols each
    const int i0 = blockIdx.y * BM;
    const int o0 = blockIdx.x * BN;

    // Global tile loading: 64 rows x 8 float4-cols; 256 threads -> 2 float4 each (A and W).
    const int lr0 = tid >> 3;       // 0..31
    const int lc  = tid & 7;        // float4 col 0..7
    const float4* A4 = reinterpret_cast<const float4*>(A);
    const float4* W4 = reinterpret_cast<const float4*>(W);

    float acc[2][2][4] = {};

    // scatter one float4 of A into fragment-ordered Sa
    auto scatA = [&](int r, float4 v) {
        #pragma unroll
        for (int q = 0; q < 4; q++) {
            float val = (q == 0) ? v.x : (q == 1) ? v.y : (q == 2) ? v.z : v.w;
            int kl = lc * 4 + q;
            int mtile = r >> 4, ktile = kl >> 3;
            int rr = r & 15, cc = kl & 7;
            int ln = ((rr & 7) << 2) | (cc & 3);
            int idx = ((cc & 4) >> 1) | ((rr & 8) >> 3);
            Sa[((mtile * 4 + ktile) * 32 + ln) * 4 + idx] = val;
        }
    };
    auto scatB = [&](int r, float4 v) {
        #pragma unroll
        for (int q = 0; q < 4; q++) {
            float val = (q == 0) ? v.x : (q == 1) ? v.y : (q == 2) ? v.z : v.w;
            int kl = lc * 4 + q;
            int ntile = r >> 3, ktile = kl >> 3;
            int n = r & 7, cc = kl & 7;
            int ln = (n << 2) | (cc & 3);
            int idx = (cc & 4) >> 2;
            Sb[((ntile * 4 + ktile) * 32 + ln) * 2 + idx] = val;
        }
    };

    // Prologue: tile 0
    {
        float4 va0 = A4[(size_t)(i0 + lr0)      * (D / 4) + lc];
        float4 va1 = A4[(size_t)(i0 + lr0 + 32) * (D / 4) + lc];
        float4 vb0 = W4[(size_t)(o0 + lr0)      * (2 * D / 4) + w_off_f4 + lc];
        float4 vb1 = W4[(size_t)(o0 + lr0 + 32) * (2 * D / 4) + w_off_f4 + lc];
        scatA(lr0, va0); scatA(lr0 + 32, va1);
        scatB(lr0, vb0); scatB(lr0 + 32, vb1);
    }
    __syncthreads();

    for (int t = 0; t < NKT; t++) {
        // prefetch next tile into registers (overlaps with MMA work)
        float4 va0, va1, vb0, vb1;
        if (t + 1 < NKT) {
            const int kc4 = (t + 1) * (BK / 4);
            va0 = A4[(size_t)(i0 + lr0)      * (D / 4) + kc4 + lc];
            va1 = A4[(size_t)(i0 + lr0 + 32) * (D / 4) + kc4 + lc];
            vb0 = W4[(size_t)(o0 + lr0)      * (2 * D / 4) + w_off_f4 + kc4 + lc];
            vb1 = W4[(size_t)(o0 + lr0 + 32) * (2 * D / 4) + w_off_f4 + kc4 + lc];
        }

        #pragma unroll
        for (int k8 = 0; k8 < 4; k8++) {
            uint32_t ahi[2][4], alo[2][4];
            #pragma unroll
            for (int mt = 0; mt < 2; mt++) {
                int mt_abs = mwarp * 2 + mt;
                float4 af = *reinterpret_cast<const float4*>(
                    &Sa[((mt_abs * 4 + k8) * 32 + lane) * 4]);
                float av[4] = {af.x, af.y, af.z, af.w};
                #pragma unroll
                for (int q = 0; q < 4; q++) {
                    ahi[mt][q] = f2tf32(av[q]);
                    alo[mt][q] = f2tf32(av[q] - __uint_as_float(ahi[mt][q]));
                }
            }
            uint32_t bhi[2][2], blo[2][2];
            #pragma unroll
            for (int nt = 0; nt < 2; nt++) {
                int nt_abs = nwarp * 2 + nt;
                float2 bf = *reinterpret_cast<const float2*>(
                    &Sb[((nt_abs * 4 + k8) * 32 + lane) * 2]);
                float bv[2] = {bf.x, bf.y};
                #pragma unroll
                for (int q = 0; q < 2; q++) {
                    bhi[nt][q] = f2tf32(bv[q]);
                    blo[nt][q] = f2tf32(bv[q] - __uint_as_float(bhi[nt][q]));
                }
            }
            #pragma unroll
            for (int mt = 0; mt < 2; mt++)
                #pragma unroll
                for (int nt = 0; nt < 2; nt++) {
                    mma_tf32(acc[mt][nt], ahi[mt], bhi[nt]);
                    mma_tf32(acc[mt][nt], alo[mt], bhi[nt]);
                    mma_tf32(acc[mt][nt], ahi[mt], blo[nt]);
                }
        }

        __syncthreads();
        if (t + 1 < NKT) {
            scatA(lr0, va0); scatA(lr0 + 32, va1);
            scatB(lr0, vb0); scatB(lr0 + 32, vb1);
            __syncthreads();
        }
    }

    // Epilogue: c0,c1 -> (row, col..col+1); c2,c3 -> (row+8, ...)
    #pragma unroll
    for (int mt = 0; mt < 2; mt++) {
        #pragma unroll
        for (int nt = 0; nt < 2; nt++) {
            int row = i0 + mwarp * 32 + mt * 16 + (lane >> 2);
            int col = o0 + nwarp * 16 + nt * 8 + 2 * (lane & 3);
            float bv0 = 0.f, bv1 = 0.f;
            if (z == 1) { bv0 = bias[col]; bv1 = bias[col + 1]; }
            float2 lo_pair = make_float2(acc[mt][nt][0] + bv0, acc[mt][nt][1] + bv1);
            float2 hi_pair = make_float2(acc[mt][nt][2] + bv0, acc[mt][nt][3] + bv1);
            *reinterpret_cast<float2*>(&C[(size_t)row * D + col]) = lo_pair;
            *reinterpret_cast<float2*>(&C[(size_t)(row + 8) * D + col]) = hi_pair;
        }
    }
}

// out[i, j, :] = lig_proj[i, :] + rec_proj[j, :]
// Block = (IBLK i's, JBLK j's), 128 threads. Each rec load serves IBLK output rows,
// cutting L2 read traffic 4x so the LTS path is free for the streaming stores.
__global__ __launch_bounds__(128) void pair_add_kernel(float4* __restrict__ out)
{
    const int c = threadIdx.x;            // float4 column 0..127
    const int i0 = blockIdx.y * IBLK;
    const int j0 = blockIdx.x * JBLK;

    const float4* lig = reinterpret_cast<const float4*>(g_lig_proj);
    const float4* rec = reinterpret_cast<const float4*>(g_rec_proj);

    float4 a[IBLK];
    #pragma unroll
    for (int u = 0; u < IBLK; u++)
        a[u] = lig[(i0 + u) * 128 + c];

    const float4* rp = rec + (size_t)j0 * 128 + c;
    float4* op = out + ((size_t)i0 * D + j0) * 128 + c;

    #pragma unroll 4
    for (int jj = 0; jj < JBLK; jj++) {
        float4 r = __ldg(rp + (size_t)jj * 128);
        #pragma unroll
        for (int u = 0; u < IBLK; u++) {
            float4 o;
            o.x = a[u].x + r.x;
            o.y = a[u].y + r.y;
            o.z = a[u].z + r.z;
            o.w = a[u].w + r.w;
            __stcs(op + ((size_t)u * D + jj) * 128, o);
        }
    }
}

extern "C" void kernel_launch(void* const* d_in, const int* in_sizes, int n_in,
                              void* d_out, int out_size)
{
    const float* lig = (const float*)d_in[0];   // (512, 512)
    const float* rec = (const float*)d_in[1];   // (512, 512)
    const float* W   = (const float*)d_in[2];   // (512, 1024)
    const float* b   = (const float*)d_in[3];   // (512,)
    float* out = (float*)d_out;                 // (512, 512, 512)

    dim3 ggrd(D / BN, D / BM, 2);   // 128 blocks
    proj_gemm_kernel<<<ggrd, 256>>>(lig, rec, W, b);

    dim3 agrd(D / JBLK, D / IBLK);  // 8 x 128 = 1024 blocks
    pair_add_kernel<<<agrd, 128>>>(reinterpret_cast<float4*>(out));
}